// round 15
// baseline (speedup 1.0000x reference)
#include <cuda_runtime.h>

#define BB 64
#define SS 129
#define FF 768
#define DD 4
#define KDIM (SS*FF)
#define N3 (3*BB)
#define MOM 0.9f
#define EPSV 1e-6f

#define XMIX_N (BB*SS*FF)
#define LOSS_OFF XMIX_N
#define NM_OFF (XMIX_N + 1)
#define NV_OFF (NM_OFF + DD*FF)

#define KSPLIT 148
#define SROWB 20
#define BUFB (N3*SROWB)
#define NPAIR 6
#define PAIRSZ 4096
#define KSLAB (NPAIR*PAIRSZ)
#define RCHUNK 37

__device__ float g_pA1[4][BB*FF];
__device__ float g_pA2[4][BB*FF];
__device__ float g_xA[BB*FF];
__device__ float g_xB[BB*FF];
__device__ float g_nm[DD*FF];
__device__ float g_nsd[DD*FF];
__device__ float g_gpart[KSPLIT*KSLAB];
__device__ float g_part2[RCHUNK][KSLAB];
__device__ float g_G[N3*N3];
__device__ float g_rowloss[N3];

__device__ __forceinline__ unsigned bfx2(float lo, float hi) {
    unsigned r;
    asm("cvt.rn.bf16x2.f32 %0, %1, %2;" : "=r"(r) : "f"(hi), "f"(lo));
    return r;
}

__device__ __forceinline__ void mma_bf16(float* d, const unsigned* a, const unsigned* b) {
    asm volatile("mma.sync.aligned.m16n8k16.row.col.f32.bf16.bf16.f32 "
        "{%0,%1,%2,%3},{%4,%5,%6,%7},{%8,%9},{%0,%1,%2,%3};"
        : "+f"(d[0]), "+f"(d[1]), "+f"(d[2]), "+f"(d[3])
        : "r"(a[0]), "r"(a[1]), "r"(a[2]), "r"(a[3]), "r"(b[0]), "r"(b[1]));
}

__device__ __forceinline__ unsigned s2u(const void* p) {
    unsigned a;
    asm("{ .reg .u64 t; cvta.to.shared.u64 t, %1; cvt.u32.u64 %0, t; }"
        : "=r"(a) : "l"(p));
    return a;
}

__device__ __forceinline__ void ldmA(unsigned* r, unsigned addr) {
    asm volatile("ldmatrix.sync.aligned.m8n8.x4.shared.b16 {%0,%1,%2,%3},[%4];"
        : "=r"(r[0]), "=r"(r[1]), "=r"(r[2]), "=r"(r[3]) : "r"(addr));
}

__device__ __forceinline__ void ldmB(unsigned* r, unsigned addr) {
    asm volatile("ldmatrix.sync.aligned.m8n8.x2.shared.b16 {%0,%1},[%2];"
        : "=r"(r[0]), "=r"(r[1]) : "r"(addr));
}

__global__ void stageA1(const float* __restrict__ x) {
    int bf = blockIdx.x;
    int seg = blockIdx.y;
    int b = bf / 3;
    int f = (bf % 3) * 256 + threadIdx.x;
    int s0 = (seg == 0) ? 0 : 33 + 32 * (seg - 1);
    int s1 = 33 + 32 * seg;
    const float* p = x + (size_t)b * KDIM + f;
    float sa = 0.f, s2a = 0.f, sb = 0.f, s2b = 0.f;
    float sc = 0.f, s2c = 0.f, sd = 0.f, s2d = 0.f;
    int ss = s0;
    for (; ss + 3 < s1; ss += 4) {
        float v0 = p[(size_t)ss * FF];
        float v1 = p[(size_t)(ss + 1) * FF];
        float v2 = p[(size_t)(ss + 2) * FF];
        float v3 = p[(size_t)(ss + 3) * FF];
        sa += v0; s2a += v0 * v0;
        sb += v1; s2b += v1 * v1;
        sc += v2; s2c += v2 * v2;
        sd += v3; s2d += v3 * v3;
    }
    for (; ss < s1; ss++) {
        float v = p[(size_t)ss * FF];
        sa += v; s2a += v * v;
    }
    int o = b * FF + f;
    g_pA1[seg][o] = (sa + sb) + (sc + sd);
    g_pA2[seg][o] = (s2a + s2b) + (s2c + s2d);
}

__global__ void stageAB(const float* __restrict__ mean_buf,
                        const float* __restrict__ var_buf,
                        const int* __restrict__ domain,
                        const int* __restrict__ drand,
                        const float* __restrict__ lmda,
                        float* __restrict__ out) {
    __shared__ float s1s[64][65];
    __shared__ float s2s[64][65];
    __shared__ float nm_s[4][64];
    __shared__ float sd_s[4][64];
    __shared__ int doms[64];
    __shared__ int dss[64];
    __shared__ float lms[64];
    int tid = threadIdx.x;
    int f0 = blockIdx.x * 64;
    if (tid < 64) {
        doms[tid] = domain[tid];
        dss[tid] = (domain[tid] + drand[tid]) & 3;
        lms[tid] = lmda[tid];
    }
    __syncthreads();
    #pragma unroll
    for (int i = 0; i < 16; i++) {
        int e = tid + 256 * i;
        int b = e >> 6, f = e & 63;
        int idx = b * FF + f0 + f;
        float s  = g_pA1[0][idx] + g_pA1[1][idx] + g_pA1[2][idx] + g_pA1[3][idx];
        float s2 = g_pA2[0][idx] + g_pA2[1][idx] + g_pA2[2][idx] + g_pA2[3][idx];
        s1s[b][f] = s;
        s2s[b][f] = s2;
    }
    __syncthreads();
    {
        int d = tid >> 6, f = tid & 63;
        float s1 = 0.f, s2 = 0.f;
        int nb = 0;
        #pragma unroll 8
        for (int b = 0; b < BB; b++) {
            if (doms[b] == d) {
                nb++;
                s1 += s1s[b][f];
                s2 += s2s[b][f];
            }
        }
        float n = (float)nb * (float)SS;
        float mu = s1 / fmaxf(n, 1.f);
        float var = (s2 - n * mu * mu) / fmaxf(n - 1.f, 1.f);
        int idx = d * FF + f0 + f;
        float nm, nv;
        if (nb > 0) {
            nm = MOM * mean_buf[idx] + (1.f - MOM) * mu;
            nv = MOM * var_buf[idx] + (1.f - MOM) * var;
        } else {
            nm = mean_buf[idx];
            nv = var_buf[idx];
        }
        out[NM_OFF + idx] = nm;
        out[NV_OFF + idx] = nv;
        float sd = sqrtf(nv + EPSV);
        g_nm[idx] = nm;
        g_nsd[idx] = sd;
        nm_s[d][f] = nm;
        sd_s[d][f] = sd;
    }
    __syncthreads();
    #pragma unroll
    for (int i = 0; i < 16; i++) {
        int e = tid + 256 * i;
        int b = e >> 6, f = e & 63;
        float s = s1s[b][f], s2 = s2s[b][f];
        float mu = s / (float)SS;
        float var = (s2 - (float)SS * mu * mu) / (float)(SS - 1);
        float inv = rsqrtf(var + EPSV);
        int ds = dss[b];
        float lm = lms[b], il = 1.f - lm;
        float isd = inv * sd_s[ds][f];
        int idx = b * FF + f0 + f;
        g_xA[idx] = lm + il * isd;
        g_xB[idx] = il * (nm_s[ds][f] - mu * isd);
    }
}

// fused gram (bf16 mma + ldmatrix) + xmix + hg. 148 CTAs x 256 threads.
__global__ __launch_bounds__(256, 1)
void gram_tc(const float* __restrict__ x,
             const float* __restrict__ hgn,
             const int* __restrict__ domain,
             float* __restrict__ out) {
    extern __shared__ unsigned sbuf[];
    int tid = threadIdx.x;
    int ks = blockIdx.x;
    int start = ks * 20 + (ks < 136 ? ks : 136);
    int ntile = (ks < 136) ? 21 : 20;
    long kbase = (long)start * 32;

    const float* p[6];
    int soff[6];
    #pragma unroll
    for (int i = 0; i < 6; i++) {
        int e = tid + 256 * i;
        int row = e >> 3, q = e & 7;
        const float* src;
        if (row < 128) src = x + (size_t)(row & 63) * KDIM;
        else           src = hgn + (size_t)(row - 128) * KDIM;
        p[i] = src + kbase + q * 4;
        soff[i] = row * SROWB + q * 2;
    }
    int offm[2], offdh[2];
    float* outp[2];
    #pragma unroll
    for (int j = 0; j < 2; j++) {
        int e = tid + 256 * (2 + j);
        int row = e >> 3, q = e & 7, b = row - 64;
        offm[j] = b * FF + q * 4;
        outp[j] = out + (size_t)b * KDIM + kbase + q * 4;
    }
    #pragma unroll
    for (int j = 0; j < 2; j++) {
        int e = tid + 256 * (4 + j);
        int b = (e >> 3) - 128, q = e & 7;
        offdh[j] = domain[b] * FF + q * 4;
    }

    int wid = tid >> 5, lane = tid & 31;
    int wm = wid >> 2, wn = wid & 3;
    const int TI[NPAIR] = {0,0,0,1,1,2};
    const int TJ[NPAIR] = {0,1,2,1,2,2};
    float acc[NPAIR][2][2][4];
    #pragma unroll
    for (int pp = 0; pp < NPAIR; pp++)
        #pragma unroll
        for (int mt = 0; mt < 2; mt++)
            #pragma unroll
            for (int nt = 0; nt < 2; nt++)
                #pragma unroll
                for (int r = 0; r < 4; r++) acc[pp][mt][nt][r] = 0.f;

    // ldmatrix per-lane base byte-offsets (within a buffer)
    unsigned sbase = s2u(sbuf);
    unsigned aoff = ((unsigned)(wm * 32 + (lane & 15)) * SROWB + (lane >> 4) * 4) * 4;
    unsigned boff = ((unsigned)(wn * 16 + (lane & 7)) * SROWB + ((lane >> 3) & 1) * 4) * 4;

    float4 v[6];
    #pragma unroll
    for (int i = 0; i < 6; i++) v[i] = *(const float4*)(p[i]);
    int fm = start % 24;

    for (int t = 0; t < ntile; t++) {
        unsigned* bb = sbuf + (t & 1) * BUFB;
        unsigned bufb = sbase + (t & 1) * (BUFB * 4);
        int fo = fm * 32;
        fm = (fm + 1 == 24) ? 0 : fm + 1;
        float4 w[6];
        w[0] = v[0]; w[1] = v[1];
        #pragma unroll
        for (int j = 0; j < 2; j++) {
            float4 xv = v[2 + j];
            float4 A  = *(const float4*)(g_xA + offm[j] + fo);
            float4 Bc = *(const float4*)(g_xB + offm[j] + fo);
            float4 xm;
            xm.x = fmaf(A.x, xv.x, Bc.x);
            xm.y = fmaf(A.y, xv.y, Bc.y);
            xm.z = fmaf(A.z, xv.z, Bc.z);
            xm.w = fmaf(A.w, xv.w, Bc.w);
            *(float4*)(outp[j] + t * 32) = xm;
            w[2 + j] = xm;
        }
        #pragma unroll
        for (int j = 0; j < 2; j++) {
            float4 nz = v[4 + j];
            float4 nm = *(const float4*)(g_nm  + offdh[j] + fo);
            float4 sd = *(const float4*)(g_nsd + offdh[j] + fo);
            float4 hg;
            hg.x = fmaf(sd.x, nz.x, nm.x);
            hg.y = fmaf(sd.y, nz.y, nm.y);
            hg.z = fmaf(sd.z, nz.z, nm.z);
            hg.w = fmaf(sd.w, nz.w, nm.w);
            w[4 + j] = hg;
        }
        #pragma unroll
        for (int i = 0; i < 6; i++) {
            uint2 u;
            u.x = bfx2(w[i].x, w[i].y);
            u.y = bfx2(w[i].z, w[i].w);
            *(uint2*)(&bb[soff[i]]) = u;
        }
        if (t + 1 < ntile) {
            #pragma unroll
            for (int i = 0; i < 6; i++) v[i] = *(const float4*)(p[i] + (t + 1) * 32);
        }
        __syncthreads();
        #pragma unroll
        for (int kk = 0; kk < 2; kk++) {
            unsigned kb = kk * 32;                    // 8 u32 = 32 bytes
            unsigned af[3][2][4], bfr[3][2][2];
            #pragma unroll
            for (int g = 0; g < 3; g++) {
                unsigned gb = (unsigned)(g * 64 * SROWB) * 4;
                #pragma unroll
                for (int mt = 0; mt < 2; mt++)
                    ldmA(af[g][mt], bufb + aoff + gb + (unsigned)(mt * 16 * SROWB) * 4 + kb);
                #pragma unroll
                for (int nt = 0; nt < 2; nt++)
                    ldmB(bfr[g][nt], bufb + boff + gb + (unsigned)(nt * 8 * SROWB) * 4 + kb);
            }
            #pragma unroll
            for (int pp = 0; pp < NPAIR; pp++)
                #pragma unroll
                for (int mt = 0; mt < 2; mt++)
                    #pragma unroll
                    for (int nt = 0; nt < 2; nt++)
                        mma_bf16(acc[pp][mt][nt], af[TI[pp]][mt], bfr[TJ[pp]][nt]);
        }
    }

    int lr = lane >> 2, lc = lane & 3;
    float* base = g_gpart + (size_t)ks * KSLAB;
    #pragma unroll
    for (int pp = 0; pp < NPAIR; pp++) {
        #pragma unroll
        for (int mt = 0; mt < 2; mt++) {
            #pragma unroll
            for (int nt = 0; nt < 2; nt++) {
                int r = wm * 32 + mt * 16 + lr;
                int c = wn * 16 + nt * 8 + lc * 2;
                float* dst = base + pp * PAIRSZ + r * 64 + c;
                *(float2*)dst = make_float2(acc[pp][mt][nt][0], acc[pp][mt][nt][1]);
                *(float2*)(dst + 8 * 64) = make_float2(acc[pp][mt][nt][2], acc[pp][mt][nt][3]);
            }
        }
    }
}

__global__ void reduceG1() {
    int i4 = (blockIdx.x * 256 + threadIdx.x) * 4;
    int c = blockIdx.y;
    const float* src = g_gpart + (size_t)(c * 4) * KSLAB + i4;
    float4 v0 = *(const float4*)(src);
    float4 v1 = *(const float4*)(src + (size_t)KSLAB);
    float4 v2 = *(const float4*)(src + (size_t)2 * KSLAB);
    float4 v3 = *(const float4*)(src + (size_t)3 * KSLAB);
    float4 r;
    r.x = (v0.x + v1.x) + (v2.x + v3.x);
    r.y = (v0.y + v1.y) + (v2.y + v3.y);
    r.z = (v0.z + v1.z) + (v2.z + v3.z);
    r.w = (v0.w + v1.w) + (v2.w + v3.w);
    *(float4*)(&g_part2[c][i4]) = r;
}

__global__ void reduceG2() {
    int idx = blockIdx.x * 256 + threadIdx.x;
    if (idx >= N3 * N3) return;
    int i = idx / N3, j = idx % N3;
    int ti = i >> 6, tj = j >> 6, li = i & 63, lj = j & 63;
    int a, b2, la, lb;
    if (ti <= tj) { a = ti; b2 = tj; la = li; lb = lj; }
    else          { a = tj; b2 = ti; la = lj; lb = li; }
    int pair = a * (5 - a) / 2 + b2;
    int o = pair * PAIRSZ + la * 64 + lb;
    float s0 = 0.f, s1 = 0.f, s2 = 0.f;
    int c = 0;
    #pragma unroll
    for (; c + 2 < RCHUNK; c += 3) {
        s0 += g_part2[c][o];
        s1 += g_part2[c + 1][o];
        s2 += g_part2[c + 2][o];
    }
    for (; c < RCHUNK; c++) s0 += g_part2[c][o];
    g_G[idx] = (s0 + s1) + s2;
}

__global__ void lossA(const int* __restrict__ labels) {
    int i = (blockIdx.x * blockDim.x + threadIdx.x) >> 5;
    int lane = threadIdx.x & 31;
    int li = (i < 2 * BB) ? labels[i & 63] : -1;
    float sqi = g_G[i * N3 + i];
    float ap = -1e30f, an = 1e30f;
    #pragma unroll
    for (int jj = 0; jj < 6; jj++) {
        int j = lane + jj * 32;
        int lj = (j < 2 * BB) ? labels[j & 63] : -1;
        float d2 = sqi + g_G[j * N3 + j] - 2.f * g_G[i * N3 + j];
        float dd = sqrtf(fmaxf(d2, 1e-12f));
        if (li == lj) ap = fmaxf(ap, dd);
        else          an = fminf(an, dd);
    }
    #pragma unroll
    for (int o = 16; o > 0; o >>= 1) {
        ap = fmaxf(ap, __shfl_xor_sync(0xFFFFFFFFu, ap, o));
        an = fminf(an, __shfl_xor_sync(0xFFFFFFFFu, an, o));
    }
    if (lane == 0) {
        float z = ap - an;
        g_rowloss[i] = (z > 0.f) ? (z + log1pf(expf(-z))) : log1pf(expf(z));
    }
}

__global__ void lossB(float* __restrict__ out) {
    __shared__ float red[256];
    int t = threadIdx.x;
    red[t] = (t < N3) ? g_rowloss[t] : 0.f;
    __syncthreads();
    for (int st = 128; st > 0; st >>= 1) {
        if (t < st) red[t] += red[t + st];
        __syncthreads();
    }
    if (t == 0) out[LOSS_OFF] = red[0] / (float)N3;
}

extern "C" void kernel_launch(void* const* d_in, const int* in_sizes, int n_in,
                              void* d_out, int out_size) {
    const float* x        = (const float*)d_in[0];
    const float* lmda     = (const float*)d_in[1];
    const float* mean_buf = (const float*)d_in[2];
    const float* var_buf  = (const float*)d_in[3];
    const float* hgn      = (const float*)d_in[4];
    const int*   labels   = (const int*)d_in[5];
    const int*   domain   = (const int*)d_in[6];
    const int*   d_rand   = (const int*)d_in[7];
    float* out = (float*)d_out;

    int smem_sz = 2 * BUFB * (int)sizeof(unsigned);
    cudaFuncSetAttribute(gram_tc, cudaFuncAttributeMaxDynamicSharedMemorySize, smem_sz);

    dim3 ga(BB * 3, 4);
    stageA1<<<ga, 256>>>(x);
    stageAB<<<FF / 64, 256>>>(mean_buf, var_buf, domain, d_rand, lmda, out);
    gram_tc<<<KSPLIT, 256, smem_sz>>>(x, hgn, domain, out);
    dim3 gr(KSLAB / 1024, RCHUNK);
    reduceG1<<<gr, 256>>>();
    reduceG2<<<(N3 * N3 + 255) / 256, 256>>>();
    lossA<<<N3 / 8, 256>>>(labels);
    lossB<<<1, 256>>>(out);
}

// round 16
// speedup vs baseline: 1.0818x; 1.0818x over previous
#include <cuda_runtime.h>

#define BB 64
#define SS 129
#define FF 768
#define DD 4
#define KDIM (SS*FF)
#define N3 (3*BB)
#define MOM 0.9f
#define EPSV 1e-6f

#define XMIX_N (BB*SS*FF)
#define LOSS_OFF XMIX_N
#define NM_OFF (XMIX_N + 1)
#define NV_OFF (NM_OFF + DD*FF)

#define KSPLIT 148
#define SROWB 20
#define BUFB (N3*SROWB)
#define NPAIR 6
#define PAIRSZ 4096
#define KSLAB (NPAIR*PAIRSZ)
#define RCHUNK 37

__device__ float g_pA1[4][BB*FF];
__device__ float g_pA2[4][BB*FF];
__device__ float g_xA[BB*FF];
__device__ float g_xB[BB*FF];
__device__ float g_nm[DD*FF];
__device__ float g_nsd[DD*FF];
__device__ float g_gpart[KSPLIT*KSLAB];
__device__ float g_part2[RCHUNK][KSLAB];
__device__ float g_G[N3*N3];
__device__ float g_rowloss[N3];

__device__ __forceinline__ unsigned bfx2(float lo, float hi) {
    unsigned r;
    asm("cvt.rn.bf16x2.f32 %0, %1, %2;" : "=r"(r) : "f"(hi), "f"(lo));
    return r;
}

__device__ __forceinline__ void mma_bf16(float* d, const unsigned* a, const unsigned* b) {
    asm volatile("mma.sync.aligned.m16n8k16.row.col.f32.bf16.bf16.f32 "
        "{%0,%1,%2,%3},{%4,%5,%6,%7},{%8,%9},{%0,%1,%2,%3};"
        : "+f"(d[0]), "+f"(d[1]), "+f"(d[2]), "+f"(d[3])
        : "r"(a[0]), "r"(a[1]), "r"(a[2]), "r"(a[3]), "r"(b[0]), "r"(b[1]));
}

__global__ void stageA1(const float* __restrict__ x) {
    int bf = blockIdx.x;
    int seg = blockIdx.y;
    int b = bf / 3;
    int f = (bf % 3) * 256 + threadIdx.x;
    int s0 = (seg == 0) ? 0 : 33 + 32 * (seg - 1);
    int s1 = 33 + 32 * seg;
    const float* p = x + (size_t)b * KDIM + f;
    float sa = 0.f, s2a = 0.f, sb = 0.f, s2b = 0.f;
    float sc = 0.f, s2c = 0.f, sd = 0.f, s2d = 0.f;
    int ss = s0;
    for (; ss + 3 < s1; ss += 4) {
        float v0 = p[(size_t)ss * FF];
        float v1 = p[(size_t)(ss + 1) * FF];
        float v2 = p[(size_t)(ss + 2) * FF];
        float v3 = p[(size_t)(ss + 3) * FF];
        sa += v0; s2a += v0 * v0;
        sb += v1; s2b += v1 * v1;
        sc += v2; s2c += v2 * v2;
        sd += v3; s2d += v3 * v3;
    }
    for (; ss < s1; ss++) {
        float v = p[(size_t)ss * FF];
        sa += v; s2a += v * v;
    }
    int o = b * FF + f;
    g_pA1[seg][o] = (sa + sb) + (sc + sd);
    g_pA2[seg][o] = (s2a + s2b) + (s2c + s2d);
}

__global__ void stageAB(const float* __restrict__ mean_buf,
                        const float* __restrict__ var_buf,
                        const int* __restrict__ domain,
                        const int* __restrict__ drand,
                        const float* __restrict__ lmda,
                        float* __restrict__ out) {
    __shared__ float s1s[64][65];
    __shared__ float s2s[64][65];
    __shared__ float nm_s[4][64];
    __shared__ float sd_s[4][64];
    __shared__ int doms[64];
    __shared__ int dss[64];
    __shared__ float lms[64];
    int tid = threadIdx.x;
    int f0 = blockIdx.x * 64;
    if (tid < 64) {
        doms[tid] = domain[tid];
        dss[tid] = (domain[tid] + drand[tid]) & 3;
        lms[tid] = lmda[tid];
    }
    __syncthreads();
    #pragma unroll
    for (int i = 0; i < 16; i++) {
        int e = tid + 256 * i;
        int b = e >> 6, f = e & 63;
        int idx = b * FF + f0 + f;
        float s  = g_pA1[0][idx] + g_pA1[1][idx] + g_pA1[2][idx] + g_pA1[3][idx];
        float s2 = g_pA2[0][idx] + g_pA2[1][idx] + g_pA2[2][idx] + g_pA2[3][idx];
        s1s[b][f] = s;
        s2s[b][f] = s2;
    }
    __syncthreads();
    {
        int d = tid >> 6, f = tid & 63;
        float s1 = 0.f, s2 = 0.f;
        int nb = 0;
        #pragma unroll 8
        for (int b = 0; b < BB; b++) {
            if (doms[b] == d) {
                nb++;
                s1 += s1s[b][f];
                s2 += s2s[b][f];
            }
        }
        float n = (float)nb * (float)SS;
        float mu = s1 / fmaxf(n, 1.f);
        float var = (s2 - n * mu * mu) / fmaxf(n - 1.f, 1.f);
        int idx = d * FF + f0 + f;
        float nm, nv;
        if (nb > 0) {
            nm = MOM * mean_buf[idx] + (1.f - MOM) * mu;
            nv = MOM * var_buf[idx] + (1.f - MOM) * var;
        } else {
            nm = mean_buf[idx];
            nv = var_buf[idx];
        }
        out[NM_OFF + idx] = nm;
        out[NV_OFF + idx] = nv;
        float sd = sqrtf(nv + EPSV);
        g_nm[idx] = nm;
        g_nsd[idx] = sd;
        nm_s[d][f] = nm;
        sd_s[d][f] = sd;
    }
    __syncthreads();
    #pragma unroll
    for (int i = 0; i < 16; i++) {
        int e = tid + 256 * i;
        int b = e >> 6, f = e & 63;
        float s = s1s[b][f], s2 = s2s[b][f];
        float mu = s / (float)SS;
        float var = (s2 - (float)SS * mu * mu) / (float)(SS - 1);
        float inv = rsqrtf(var + EPSV);
        int ds = dss[b];
        float lm = lms[b], il = 1.f - lm;
        float isd = inv * sd_s[ds][f];
        int idx = b * FF + f0 + f;
        g_xA[idx] = lm + il * isd;
        g_xB[idx] = il * (nm_s[ds][f] - mu * isd);
    }
}

// fused gram (bf16 mma) + xmix + hg. 148 CTAs x 512 threads.
// Loader split across all 512 threads (1 x-row quad + 1 hgn quad each,
// x quad feeds both raw row and xmix row). MMA: 2 warp-groups x 8 warps;
// group 0 -> pairs (0,0)(0,1)(0,2), group 1 -> (1,1)(1,2)(2,2).
__global__ __launch_bounds__(512, 1)
void gram_tc(const float* __restrict__ x,
             const float* __restrict__ hgn,
             const int* __restrict__ domain,
             float* __restrict__ out) {
    extern __shared__ unsigned sbuf[];
    int tid = threadIdx.x;
    int ks = blockIdx.x;
    int start = ks * 20 + (ks < 136 ? ks : 136);
    int ntile = (ks < 136) ? 21 : 20;
    long kbase = (long)start * 32;

    // ---- loader: thread (r = tid>>3, q = tid&7), 64x8 = 512 exactly ----
    int r = tid >> 3, q = tid & 7;
    int q4 = q * 4;
    const float* px = x   + (size_t)r * KDIM + kbase + q4;
    const float* ph = hgn + (size_t)r * KDIM + kbase + q4;
    float* outp     = out + (size_t)r * KDIM + kbase + q4;
    int offm  = r * FF + q4;
    int offdh = domain[r] * FF + q4;
    int soff0 = r * SROWB + q * 2;            // raw x row
    int soff1 = (64 + r) * SROWB + q * 2;     // xmix row
    int soff2 = (128 + r) * SROWB + q * 2;    // hg row

    // ---- mma setup ----
    int wid = tid >> 5, lane = tid & 31;
    int grp = wid >> 3, wq = wid & 7;
    int wm = wq >> 2, wn = wq & 3;            // 2x4 warps over 64x64
    int lr = lane >> 2, lc = lane & 3;
    float acc[3][2][2][4];
    #pragma unroll
    for (int pp = 0; pp < 3; pp++)
        #pragma unroll
        for (int mt = 0; mt < 2; mt++)
            #pragma unroll
            for (int nt = 0; nt < 2; nt++)
                #pragma unroll
                for (int rr = 0; rr < 4; rr++) acc[pp][mt][nt][rr] = 0.f;

    float4 vx = *(const float4*)px;
    float4 vh = *(const float4*)ph;
    int fm = start % 24;

    for (int t = 0; t < ntile; t++) {
        unsigned* bb = sbuf + (t & 1) * BUFB;
        int fo = fm * 32;
        fm = (fm + 1 == 24) ? 0 : fm + 1;
        // xmix via precomputed A/B (reuses vx)
        float4 A  = *(const float4*)(g_xA + offm + fo);
        float4 Bc = *(const float4*)(g_xB + offm + fo);
        float4 xm;
        xm.x = fmaf(A.x, vx.x, Bc.x);
        xm.y = fmaf(A.y, vx.y, Bc.y);
        xm.z = fmaf(A.z, vx.z, Bc.z);
        xm.w = fmaf(A.w, vx.w, Bc.w);
        *(float4*)(outp + t * 32) = xm;
        // hg
        float4 nm = *(const float4*)(g_nm  + offdh + fo);
        float4 sd = *(const float4*)(g_nsd + offdh + fo);
        float4 hg;
        hg.x = fmaf(sd.x, vh.x, nm.x);
        hg.y = fmaf(sd.y, vh.y, nm.y);
        hg.z = fmaf(sd.z, vh.z, nm.z);
        hg.w = fmaf(sd.w, vh.w, nm.w);
        // bf16 convert + 3 STS.64
        uint2 u;
        u.x = bfx2(vx.x, vx.y); u.y = bfx2(vx.z, vx.w);
        *(uint2*)(&bb[soff0]) = u;
        u.x = bfx2(xm.x, xm.y); u.y = bfx2(xm.z, xm.w);
        *(uint2*)(&bb[soff1]) = u;
        u.x = bfx2(hg.x, hg.y); u.y = bfx2(hg.z, hg.w);
        *(uint2*)(&bb[soff2]) = u;
        // prefetch t+1
        if (t + 1 < ntile) {
            vx = *(const float4*)(px + (t + 1) * 32);
            vh = *(const float4*)(ph + (t + 1) * 32);
        }
        __syncthreads();
        const unsigned* S = bb;
        if (grp == 0) {
            #pragma unroll
            for (int kk = 0; kk < 2; kk++) {
                int ku = kk * 8;
                unsigned af[2][4], bfr[3][2][2];
                #pragma unroll
                for (int mt = 0; mt < 2; mt++) {
                    int r0 = wm * 32 + mt * 16 + lr;
                    af[mt][0] = S[r0 * SROWB + ku + lc];
                    af[mt][1] = S[(r0 + 8) * SROWB + ku + lc];
                    af[mt][2] = S[r0 * SROWB + ku + lc + 4];
                    af[mt][3] = S[(r0 + 8) * SROWB + ku + lc + 4];
                }
                #pragma unroll
                for (int g = 0; g < 3; g++)
                    #pragma unroll
                    for (int nt = 0; nt < 2; nt++) {
                        int n0 = g * 64 + wn * 16 + nt * 8 + lr;
                        bfr[g][nt][0] = S[n0 * SROWB + ku + lc];
                        bfr[g][nt][1] = S[n0 * SROWB + ku + lc + 4];
                    }
                #pragma unroll
                for (int pp = 0; pp < 3; pp++)
                    #pragma unroll
                    for (int mt = 0; mt < 2; mt++)
                        #pragma unroll
                        for (int nt = 0; nt < 2; nt++)
                            mma_bf16(acc[pp][mt][nt], af[mt], bfr[pp][nt]);
            }
        } else {
            #pragma unroll
            for (int kk = 0; kk < 2; kk++) {
                int ku = kk * 8;
                unsigned af[2][2][4], bfr[2][2][2];
                #pragma unroll
                for (int ga = 0; ga < 2; ga++)
                    #pragma unroll
                    for (int mt = 0; mt < 2; mt++) {
                        int r0 = (ga + 1) * 64 + wm * 32 + mt * 16 + lr;
                        af[ga][mt][0] = S[r0 * SROWB + ku + lc];
                        af[ga][mt][1] = S[(r0 + 8) * SROWB + ku + lc];
                        af[ga][mt][2] = S[r0 * SROWB + ku + lc + 4];
                        af[ga][mt][3] = S[(r0 + 8) * SROWB + ku + lc + 4];
                    }
                #pragma unroll
                for (int gb = 0; gb < 2; gb++)
                    #pragma unroll
                    for (int nt = 0; nt < 2; nt++) {
                        int n0 = (gb + 1) * 64 + wn * 16 + nt * 8 + lr;
                        bfr[gb][nt][0] = S[n0 * SROWB + ku + lc];
                        bfr[gb][nt][1] = S[n0 * SROWB + ku + lc + 4];
                    }
                const int PA[3] = {0, 0, 1};
                const int PB[3] = {0, 1, 1};
                #pragma unroll
                for (int pp = 0; pp < 3; pp++)
                    #pragma unroll
                    for (int mt = 0; mt < 2; mt++)
                        #pragma unroll
                        for (int nt = 0; nt < 2; nt++)
                            mma_bf16(acc[pp][mt][nt], af[PA[pp]][mt], bfr[PB[pp]][nt]);
            }
        }
    }

    // epilogue: group 0 -> pairs 0,1,2 ; group 1 -> pairs 3,4,5
    float* base = g_gpart + (size_t)ks * KSLAB + (grp * 3) * PAIRSZ;
    #pragma unroll
    for (int pp = 0; pp < 3; pp++) {
        #pragma unroll
        for (int mt = 0; mt < 2; mt++) {
            #pragma unroll
            for (int nt = 0; nt < 2; nt++) {
                int rr = wm * 32 + mt * 16 + lr;
                int c = wn * 16 + nt * 8 + lc * 2;
                float* dst = base + pp * PAIRSZ + rr * 64 + c;
                *(float2*)dst = make_float2(acc[pp][mt][nt][0], acc[pp][mt][nt][1]);
                *(float2*)(dst + 8 * 64) = make_float2(acc[pp][mt][nt][2], acc[pp][mt][nt][3]);
            }
        }
    }
}

__global__ void reduceG1() {
    int i4 = (blockIdx.x * 256 + threadIdx.x) * 4;
    int c = blockIdx.y;
    const float* src = g_gpart + (size_t)(c * 4) * KSLAB + i4;
    float4 v0 = *(const float4*)(src);
    float4 v1 = *(const float4*)(src + (size_t)KSLAB);
    float4 v2 = *(const float4*)(src + (size_t)2 * KSLAB);
    float4 v3 = *(const float4*)(src + (size_t)3 * KSLAB);
    float4 rr;
    rr.x = (v0.x + v1.x) + (v2.x + v3.x);
    rr.y = (v0.y + v1.y) + (v2.y + v3.y);
    rr.z = (v0.z + v1.z) + (v2.z + v3.z);
    rr.w = (v0.w + v1.w) + (v2.w + v3.w);
    *(float4*)(&g_part2[c][i4]) = rr;
}

__global__ void reduceG2() {
    int idx = blockIdx.x * 256 + threadIdx.x;
    if (idx >= N3 * N3) return;
    int i = idx / N3, j = idx % N3;
    int ti = i >> 6, tj = j >> 6, li = i & 63, lj = j & 63;
    int a, b2, la, lb;
    if (ti <= tj) { a = ti; b2 = tj; la = li; lb = lj; }
    else          { a = tj; b2 = ti; la = lj; lb = li; }
    int pair = a * (5 - a) / 2 + b2;
    int o = pair * PAIRSZ + la * 64 + lb;
    float s0 = 0.f, s1 = 0.f, s2 = 0.f;
    int c = 0;
    #pragma unroll
    for (; c + 2 < RCHUNK; c += 3) {
        s0 += g_part2[c][o];
        s1 += g_part2[c + 1][o];
        s2 += g_part2[c + 2][o];
    }
    for (; c < RCHUNK; c++) s0 += g_part2[c][o];
    g_G[idx] = (s0 + s1) + s2;
}

__global__ void lossA(const int* __restrict__ labels) {
    int i = (blockIdx.x * blockDim.x + threadIdx.x) >> 5;
    int lane = threadIdx.x & 31;
    int li = (i < 2 * BB) ? labels[i & 63] : -1;
    float sqi = g_G[i * N3 + i];
    float ap = -1e30f, an = 1e30f;
    #pragma unroll
    for (int jj = 0; jj < 6; jj++) {
        int j = lane + jj * 32;
        int lj = (j < 2 * BB) ? labels[j & 63] : -1;
        float d2 = sqi + g_G[j * N3 + j] - 2.f * g_G[i * N3 + j];
        float dd = sqrtf(fmaxf(d2, 1e-12f));
        if (li == lj) ap = fmaxf(ap, dd);
        else          an = fminf(an, dd);
    }
    #pragma unroll
    for (int o = 16; o > 0; o >>= 1) {
        ap = fmaxf(ap, __shfl_xor_sync(0xFFFFFFFFu, ap, o));
        an = fminf(an, __shfl_xor_sync(0xFFFFFFFFu, an, o));
    }
    if (lane == 0) {
        float z = ap - an;
        g_rowloss[i] = (z > 0.f) ? (z + log1pf(expf(-z))) : log1pf(expf(z));
    }
}

__global__ void lossB(float* __restrict__ out) {
    __shared__ float red[256];
    int t = threadIdx.x;
    red[t] = (t < N3) ? g_rowloss[t] : 0.f;
    __syncthreads();
    for (int st = 128; st > 0; st >>= 1) {
        if (t < st) red[t] += red[t + st];
        __syncthreads();
    }
    if (t == 0) out[LOSS_OFF] = red[0] / (float)N3;
}

extern "C" void kernel_launch(void* const* d_in, const int* in_sizes, int n_in,
                              void* d_out, int out_size) {
    const float* x        = (const float*)d_in[0];
    const float* lmda     = (const float*)d_in[1];
    const float* mean_buf = (const float*)d_in[2];
    const float* var_buf  = (const float*)d_in[3];
    const float* hgn      = (const float*)d_in[4];
    const int*   labels   = (const int*)d_in[5];
    const int*   domain   = (const int*)d_in[6];
    const int*   d_rand   = (const int*)d_in[7];
    float* out = (float*)d_out;

    int smem_sz = 2 * BUFB * (int)sizeof(unsigned);
    cudaFuncSetAttribute(gram_tc, cudaFuncAttributeMaxDynamicSharedMemorySize, smem_sz);

    dim3 ga(BB * 3, 4);
    stageA1<<<ga, 256>>>(x);
    stageAB<<<FF / 64, 256>>>(mean_buf, var_buf, domain, d_rand, lmda, out);
    gram_tc<<<KSPLIT, 512, smem_sz>>>(x, hgn, domain, out);
    dim3 gr(KSLAB / 1024, RCHUNK);
    reduceG1<<<gr, 256>>>();
    reduceG2<<<(N3 * N3 + 255) / 256, 256>>>();
    lossA<<<N3 / 8, 256>>>(labels);
    lossB<<<1, 256>>>(out);
}